// round 1
// baseline (speedup 1.0000x reference)
#include <cuda_runtime.h>
#include <math.h>

// ---------------------------------------------------------------------------
// Scratch (device globals: no allocation allowed anywhere)
// Sized for B=4, S=4096, D=512 -> M = 16384 tokens.
// ---------------------------------------------------------------------------
#define MAXELEM (16384 * 512)
#define MAXPH   (4096 * 512)

__device__ float g_buf[6][MAXELEM];   // K, V, Q, KM, QM, N(normed)
__device__ float g_cb[MAXPH];         // cos(base_phase)
__device__ float g_sb[MAXPH];         // sin(base_phase)

// ---------------------------------------------------------------------------
// Kernel 0: precompute cos/sin of base phases (accurate sincosf, runs once
// per launch over S*D = 2M elements; negligible cost)
// ---------------------------------------------------------------------------
__global__ void phase_table_kernel(const float* __restrict__ bp,
                                   float* __restrict__ cb,
                                   float* __restrict__ sb, int n) {
    int i = blockIdx.x * blockDim.x + threadIdx.x;
    if (i < n) {
        float s, c;
        sincosf(bp[i], &s, &c);
        cb[i] = c;
        sb[i] = s;
    }
}

// ---------------------------------------------------------------------------
// SGEMM (NT): C[m,n] = bias[n] + sum_k A[m,k] * W[n,k]  (+ resid[m,n])
// A: [M,K] row-major, W: [N,K] row-major (torch Linear weight layout).
// 128x128 block tile, BK=8, 256 threads, 8x8 microtile.
// Requires M%128==0, N%128==0, K%8==0 (true: 16384, 512, 512).
// ---------------------------------------------------------------------------
#define BM 128
#define BN 128
#define BK 8

__global__ __launch_bounds__(256, 2) void sgemm_nt(
    const float* __restrict__ A, const float* __restrict__ W,
    const float* __restrict__ bias, const float* __restrict__ resid,
    float* __restrict__ C, int M, int N, int K)
{
    __shared__ float As[BK][BM + 4];
    __shared__ float Bs[BK][BN + 4];

    const int bm = blockIdx.y * BM;
    const int bn = blockIdx.x * BN;
    const int tid = threadIdx.x;

    // loader mapping: each thread loads one float4 of A and one of W per k-step
    const int lrow = tid >> 1;          // 0..127
    const int lseg = (tid & 1) * 4;     // 0 or 4

    // compute mapping: 16x16 thread grid, 8x8 microtile
    const int ty = tid >> 4;            // 0..15
    const int tx = tid & 15;            // 0..15

    float acc[8][8];
#pragma unroll
    for (int i = 0; i < 8; i++)
#pragma unroll
        for (int j = 0; j < 8; j++) acc[i][j] = 0.f;

    const float* Aload = A + (long)(bm + lrow) * K + lseg;
    const float* Wload = W + (long)(bn + lrow) * K + lseg;

    for (int k0 = 0; k0 < K; k0 += BK) {
        float4 a4 = *(const float4*)(Aload + k0);
        float4 b4 = *(const float4*)(Wload + k0);
        As[lseg + 0][lrow] = a4.x;
        As[lseg + 1][lrow] = a4.y;
        As[lseg + 2][lrow] = a4.z;
        As[lseg + 3][lrow] = a4.w;
        Bs[lseg + 0][lrow] = b4.x;
        Bs[lseg + 1][lrow] = b4.y;
        Bs[lseg + 2][lrow] = b4.z;
        Bs[lseg + 3][lrow] = b4.w;
        __syncthreads();

#pragma unroll
        for (int kk = 0; kk < BK; kk++) {
            float a[8], b[8];
            *(float4*)(a)     = *(const float4*)(&As[kk][ty * 8]);
            *(float4*)(a + 4) = *(const float4*)(&As[kk][ty * 8 + 4]);
            *(float4*)(b)     = *(const float4*)(&Bs[kk][tx * 8]);
            *(float4*)(b + 4) = *(const float4*)(&Bs[kk][tx * 8 + 4]);
#pragma unroll
            for (int i = 0; i < 8; i++)
#pragma unroll
                for (int j = 0; j < 8; j++)
                    acc[i][j] = fmaf(a[i], b[j], acc[i][j]);
        }
        __syncthreads();
    }

    // epilogue
    float bvals[8];
#pragma unroll
    for (int j = 0; j < 8; j++) bvals[j] = bias[bn + tx * 8 + j];

#pragma unroll
    for (int i = 0; i < 8; i++) {
        int m = bm + ty * 8 + i;
        long off = (long)m * N + bn + tx * 8;
        float4 o0, o1;
        o0.x = acc[i][0] + bvals[0];
        o0.y = acc[i][1] + bvals[1];
        o0.z = acc[i][2] + bvals[2];
        o0.w = acc[i][3] + bvals[3];
        o1.x = acc[i][4] + bvals[4];
        o1.y = acc[i][5] + bvals[5];
        o1.z = acc[i][6] + bvals[6];
        o1.w = acc[i][7] + bvals[7];
        if (resid) {
            float4 r0 = *(const float4*)(resid + off);
            float4 r1 = *(const float4*)(resid + off + 4);
            o0.x += r0.x; o0.y += r0.y; o0.z += r0.z; o0.w += r0.w;
            o1.x += r1.x; o1.y += r1.y; o1.z += r1.z; o1.w += r1.w;
        }
        *(float4*)(C + off)     = o0;
        *(float4*)(C + off + 4) = o1;
    }
}

// ---------------------------------------------------------------------------
// Taylor sincos for tiny delta (|x| << 1; modulation is ~N(0, 0.02))
// abs error < 3e-6 even at |x|=1.
// ---------------------------------------------------------------------------
__device__ __forceinline__ void sincos_small(float x, float& s, float& c) {
    float x2 = x * x;
    s = x * fmaf(x2, fmaf(x2, fmaf(x2, -1.f / 5040.f, 1.f / 120.f), -1.f / 6.f), 1.f);
    c = fmaf(x2, fmaf(x2, fmaf(x2, -1.f / 720.f, 1.f / 24.f), -0.5f), 1.f);
}

// ---------------------------------------------------------------------------
// Fused phasor bind + chunked cumsum + retrieval + LayerNorm.
// Block = one (batch, chunk); blockDim.x = D threads (one per feature).
// Each thread carries the cumulative (mem_real, mem_imag) for its d across
// the 64 positions of the chunk; per position, a block-wide reduction gives
// LayerNorm mean/var. Writes normed activations.
// ---------------------------------------------------------------------------
__global__ void phasor_ln_kernel(
    const float* __restrict__ V, const float* __restrict__ KM,
    const float* __restrict__ QM,
    const float* __restrict__ cb, const float* __restrict__ sb,
    const float* __restrict__ msp,
    const float* __restrict__ lng, const float* __restrict__ lnb,
    float* __restrict__ O, int S, int D, int CH)
{
    const int d = threadIdx.x;
    const int nC = S / CH;
    const int b = blockIdx.x / nC;
    const int c = blockIdx.x % nC;

    const float ms  = msp[0];
    const float g   = lng[d];
    const float be  = lnb[d];
    const float inv = rsqrtf((float)D);

    const int lane = d & 31;
    const int w    = d >> 5;
    const int nw   = blockDim.x >> 5;

    __shared__ float red1[32], red2[32];

    float mr = 0.f, mi = 0.f;
    long base  = ((long)b * S + (long)c * CH) * D + d;
    long pbase = ((long)c * CH) * D + d;

    for (int s = 0; s < CH; s++) {
        long idx  = base + (long)s * D;
        long pidx = pbase + (long)s * D;

        float cbp = cb[pidx];
        float sbp = sb[pidx];
        float dk = KM[idx] * ms;
        float dq = QM[idx] * ms;
        float sk, ck, sq, cq;
        sincos_small(dk, sk, ck);
        sincos_small(dq, sq, cq);

        // angle addition: cos(bp+dk) etc.
        float ckp = cbp * ck - sbp * sk;
        float skp = sbp * ck + cbp * sk;
        float cqp = cbp * cq - sbp * sq;
        float sqp = sbp * cq + cbp * sq;

        float v = V[idx];
        mr = fmaf(v, ckp, mr);
        mi = fmaf(v, skp, mi);

        float r = (mr * cqp + mi * sqp) * inv;

        // block reduction: sum(r), sum(r^2)
        float s1 = r, s2 = r * r;
#pragma unroll
        for (int o = 16; o > 0; o >>= 1) {
            s1 += __shfl_xor_sync(0xffffffffu, s1, o);
            s2 += __shfl_xor_sync(0xffffffffu, s2, o);
        }
        if (lane == 0) { red1[w] = s1; red2[w] = s2; }
        __syncthreads();
        if (d < 32) {
            float a1 = (d < nw) ? red1[d] : 0.f;
            float a2 = (d < nw) ? red2[d] : 0.f;
#pragma unroll
            for (int o = 16; o > 0; o >>= 1) {
                a1 += __shfl_xor_sync(0xffffffffu, a1, o);
                a2 += __shfl_xor_sync(0xffffffffu, a2, o);
            }
            if (d == 0) { red1[0] = a1; red2[0] = a2; }
        }
        __syncthreads();
        float mu  = red1[0] / (float)D;
        float var = red2[0] / (float)D - mu * mu;
        __syncthreads();   // protect red[] before next iteration's writes

        float normed = (r - mu) * rsqrtf(var + 1e-5f) * g + be;
        O[idx] = normed;
    }
}

// ---------------------------------------------------------------------------
// Launch
// ---------------------------------------------------------------------------
extern "C" void kernel_launch(void* const* d_in, const int* in_sizes, int n_in,
                              void* d_out, int out_size)
{
    const float* x    = (const float*)d_in[0];
    const float* bp   = (const float*)d_in[1];
    const float* Wk   = (const float*)d_in[2];
    const float* bk   = (const float*)d_in[3];
    const float* Wv   = (const float*)d_in[4];
    const float* bv   = (const float*)d_in[5];
    const float* Wq   = (const float*)d_in[6];
    const float* bq   = (const float*)d_in[7];
    const float* Wkm  = (const float*)d_in[8];
    const float* bkm  = (const float*)d_in[9];
    const float* Wqm  = (const float*)d_in[10];
    const float* bqm  = (const float*)d_in[11];
    const float* ms   = (const float*)d_in[12];
    const float* lng  = (const float*)d_in[13];
    const float* lnb  = (const float*)d_in[14];
    const float* Wo   = (const float*)d_in[15];
    const float* bo   = (const float*)d_in[16];
    float* out = (float*)d_out;

    const int D  = in_sizes[3];            // bk: [D]
    const int SD = in_sizes[1];            // base_phases: [S,D]
    const int S  = SD / D;
    const int M  = in_sizes[0] / D;        // B*S
    const int CH = 64;

    float* bufs = nullptr;
    cudaGetSymbolAddress((void**)&bufs, g_buf);
    float* cbuf = nullptr;
    cudaGetSymbolAddress((void**)&cbuf, g_cb);
    float* sbuf = nullptr;
    cudaGetSymbolAddress((void**)&sbuf, g_sb);

    float* K  = bufs + 0L * MAXELEM;
    float* V  = bufs + 1L * MAXELEM;
    float* Q  = bufs + 2L * MAXELEM;
    float* KM = bufs + 3L * MAXELEM;
    float* QM = bufs + 4L * MAXELEM;
    float* NB = bufs + 5L * MAXELEM;

    dim3 gg(D / BN, M / BM);

    phase_table_kernel<<<(SD + 255) / 256, 256>>>(bp, cbuf, sbuf, SD);

    sgemm_nt<<<gg, 256>>>(x, Wk, bk, nullptr, K, M, D, D);
    sgemm_nt<<<gg, 256>>>(x, Wv, bv, nullptr, V, M, D, D);
    sgemm_nt<<<gg, 256>>>(x, Wq, bq, nullptr, Q, M, D, D);
    sgemm_nt<<<gg, 256>>>(K, Wkm, bkm, nullptr, KM, M, D, D);
    sgemm_nt<<<gg, 256>>>(Q, Wqm, bqm, nullptr, QM, M, D, D);

    phasor_ln_kernel<<<(M / CH), D>>>(V, KM, QM, cbuf, sbuf, ms, lng, lnb,
                                      NB, S, D, CH);

    // final projection + residual add fused into epilogue
    sgemm_nt<<<gg, 256>>>(NB, Wo, bo, x, out, M, D, D);
}

// round 3
// speedup vs baseline: 4.6336x; 4.6336x over previous
#include <cuda_runtime.h>
#include <cuda_fp16.h>
#include <math.h>
#include <stdint.h>

// ===========================================================================
// Scratch (device globals; no allocation allowed)
// B=4, S=4096, D=512 -> M = 16384
// ===========================================================================
#define MAXELEM (16384 * 512)
#define MAXPH   (4096 * 512)
#define WELEM   (512 * 512)

__device__ __align__(256) __half g_h[4][MAXELEM];    // xh, Kh, Qh, NBh
__device__ __align__(256) float  g_f32[3][MAXELEM];  // V, KM, QM
__device__ __align__(256) __half g_wh[6][WELEM];     // 6 fp16 weights
__device__ float g_cb[MAXPH];
__device__ float g_sb[MAXPH];

// ===========================================================================
// helpers
// ===========================================================================
__device__ __forceinline__ uint32_t smem_to_u32(const void* smem_ptr) {
    uint32_t addr;
    asm("{ .reg .u64 tmp; cvta.to.shared.u64 tmp, %1; cvt.u32.u64 %0, tmp; }"
        : "=r"(addr) : "l"(smem_ptr));
    return addr;
}

__device__ __forceinline__ void ldsm_x4(uint32_t& r0, uint32_t& r1,
                                        uint32_t& r2, uint32_t& r3, uint32_t a) {
    asm volatile("ldmatrix.sync.aligned.m8n8.x4.shared.b16 {%0,%1,%2,%3}, [%4];\n"
                 : "=r"(r0), "=r"(r1), "=r"(r2), "=r"(r3) : "r"(a));
}

__device__ __forceinline__ void mma16816(float* c, const uint32_t* a,
                                         const uint32_t* b) {
    asm volatile(
        "mma.sync.aligned.m16n8k16.row.col.f32.f16.f16.f32 "
        "{%0,%1,%2,%3},{%4,%5,%6,%7},{%8,%9},{%0,%1,%2,%3};\n"
        : "+f"(c[0]), "+f"(c[1]), "+f"(c[2]), "+f"(c[3])
        : "r"(a[0]), "r"(a[1]), "r"(a[2]), "r"(a[3]), "r"(b[0]), "r"(b[1]));
}

// ===========================================================================
// base-phase cos/sin table
// ===========================================================================
__global__ void phase_table_kernel(const float* __restrict__ bp,
                                   float* __restrict__ cb,
                                   float* __restrict__ sb, int n) {
    int i = blockIdx.x * blockDim.x + threadIdx.x;
    if (i < n) {
        float s, c;
        sincosf(bp[i], &s, &c);
        cb[i] = c;
        sb[i] = s;
    }
}

// ===========================================================================
// fp32 -> fp16 (vectorized; n % 4 == 0)
// ===========================================================================
__global__ void tohalf_kernel(const float4* __restrict__ src,
                              __half2* __restrict__ dst, int n4) {
    int i = blockIdx.x * blockDim.x + threadIdx.x;
    if (i < n4) {
        float4 v = src[i];
        dst[2 * i + 0] = __floats2half2_rn(v.x, v.y);
        dst[2 * i + 1] = __floats2half2_rn(v.z, v.w);
    }
}

// ===========================================================================
// fp16 HMMA GEMM (NT): C[m,n] = bias[n] + A[m,:] . W[n,:]  (+ resid)
//   A [M,K] fp16 row-major, W [N,K] fp16 row-major
// Tile 128x128, KC=64, 256 threads (8 warps 2x4, each 64x32),
// 2-stage cp.async pipeline, padded smem rows (144B) -> conflict-free ldmatrix.
// mode 0: outF = acc + bias
// mode 1: outH = fp16(acc + bias)
// mode 2: outF = acc + bias + resid
// ===========================================================================
#define KC 64
#define ROWB 144                   // 128B data + 16B pad
#define TILE_B (128 * ROWB)        // 18432
#define STAGE_B (2 * TILE_B)       // A + W
#define GEMM_SMEM (2 * STAGE_B)    // 73728

__global__ __launch_bounds__(256) void gemm_h(
    const __half* __restrict__ A, const __half* __restrict__ W,
    const float* __restrict__ bias, const float* __restrict__ resid,
    float* __restrict__ outF, __half* __restrict__ outH,
    int M, int N, int K, int mode)
{
    extern __shared__ char smem[];
    const uint32_t sbase = smem_to_u32(smem);
    const int tid = threadIdx.x;
    const int wid = tid >> 5, lane = tid & 31;
    const int bm = blockIdx.y * 128;
    const int bn = blockIdx.x * 128;
    const int wm = wid >> 2, wn = wid & 3;
    const int NCH = K / KC;

    const __half* Ab = A + (size_t)bm * K;
    const __half* Wb = W + (size_t)bn * K;

    auto load_chunk = [&](int kc, int s) {
        uint32_t st = sbase + s * STAGE_B;
        int koff = kc * KC;
        #pragma unroll
        for (int j = 0; j < 8; j++) {
            int q = tid + j * 256;
            int t = q >> 10;               // 0 = A tile, 1 = W tile
            int r = (q >> 3) & 127;
            int seg = q & 7;
            const __half* src = (t ? Wb : Ab) + (size_t)r * K + koff + seg * 8;
            uint32_t dst = st + t * TILE_B + r * ROWB + seg * 16;
            asm volatile("cp.async.cg.shared.global [%0], [%1], 16;\n"
                         :: "r"(dst), "l"(src));
        }
        asm volatile("cp.async.commit_group;\n");
    };

    float acc[4][4][4];
    #pragma unroll
    for (int i = 0; i < 4; i++)
        #pragma unroll
        for (int j = 0; j < 4; j++)
            #pragma unroll
            for (int e = 0; e < 4; e++) acc[i][j][e] = 0.f;

    load_chunk(0, 0);
    load_chunk(1, 1);

    const uint32_t a_r = (lane & 15);
    const uint32_t a_k = (lane >> 4) * 16;
    const uint32_t b_r = (lane & 7) + ((lane >> 4) << 3);
    const uint32_t b_k = ((lane >> 3) & 1) * 16;

    for (int i = 0; i < NCH; i++) {
        int s = i & 1;
        if (i == NCH - 1)
            asm volatile("cp.async.wait_group 0;\n" ::: "memory");
        else
            asm volatile("cp.async.wait_group 1;\n" ::: "memory");
        __syncthreads();

        uint32_t At = sbase + s * STAGE_B;
        uint32_t Wt = At + TILE_B;

        #pragma unroll
        for (int k16 = 0; k16 < 4; k16++) {
            uint32_t a[4][4];
            #pragma unroll
            for (int mi = 0; mi < 4; mi++) {
                uint32_t addr = At + (wm * 64 + mi * 16 + a_r) * ROWB
                              + k16 * 32 + a_k;
                ldsm_x4(a[mi][0], a[mi][1], a[mi][2], a[mi][3], addr);
            }
            uint32_t b[4][2];
            #pragma unroll
            for (int bp = 0; bp < 2; bp++) {
                uint32_t r0, r1, r2, r3;
                uint32_t addr = Wt + (wn * 32 + bp * 16 + b_r) * ROWB
                              + k16 * 32 + b_k;
                ldsm_x4(r0, r1, r2, r3, addr);
                b[2 * bp + 0][0] = r0; b[2 * bp + 0][1] = r1;
                b[2 * bp + 1][0] = r2; b[2 * bp + 1][1] = r3;
            }
            #pragma unroll
            for (int mi = 0; mi < 4; mi++)
                #pragma unroll
                for (int ni = 0; ni < 4; ni++)
                    mma16816(acc[mi][ni], a[mi], b[ni]);
        }
        __syncthreads();
        if (i + 2 < NCH) load_chunk(i + 2, s);
    }

    // epilogue: direct stores, 8B per thread per frag-half
    const int r0 = bm + wm * 64 + (lane >> 2);
    const int c0 = bn + wn * 32 + (lane & 3) * 2;
    #pragma unroll
    for (int mi = 0; mi < 4; mi++) {
        #pragma unroll
        for (int h = 0; h < 2; h++) {
            int row = r0 + mi * 16 + h * 8;
            #pragma unroll
            for (int ni = 0; ni < 4; ni++) {
                int col = c0 + ni * 8;
                size_t idx = (size_t)row * N + col;
                float2 bv = *(const float2*)(bias + col);
                float v0 = acc[mi][ni][2 * h + 0] + bv.x;
                float v1 = acc[mi][ni][2 * h + 1] + bv.y;
                if (mode == 2) {
                    float2 rv = *(const float2*)(resid + idx);
                    v0 += rv.x; v1 += rv.y;
                }
                if (mode == 1) {
                    *(__half2*)(outH + idx) = __floats2half2_rn(v0, v1);
                } else {
                    float2 o; o.x = v0; o.y = v1;
                    *(float2*)(outF + idx) = o;
                }
            }
        }
    }
}

// ===========================================================================
// Taylor sincos for tiny delta (|x| << 1)
// ===========================================================================
__device__ __forceinline__ void sincos_small(float x, float& s, float& c) {
    float x2 = x * x;
    s = x * fmaf(x2, fmaf(x2, fmaf(x2, -1.f / 5040.f, 1.f / 120.f), -1.f / 6.f), 1.f);
    c = fmaf(x2, fmaf(x2, fmaf(x2, -1.f / 720.f, 1.f / 24.f), -0.5f), 1.f);
}

// ===========================================================================
// Fused phasor bind + chunked cumsum + retrieval + LayerNorm -> fp16 out
// Block = one (batch, chunk); 512 threads = one per feature d.
// ===========================================================================
__global__ void phasor_ln_kernel(
    const float* __restrict__ V, const float* __restrict__ KM,
    const float* __restrict__ QM,
    const float* __restrict__ cb, const float* __restrict__ sbp_,
    const float* __restrict__ msp,
    const float* __restrict__ lng, const float* __restrict__ lnb,
    __half* __restrict__ Oh, int S, int D, int CH)
{
    const int d = threadIdx.x;
    const int nC = S / CH;
    const int b = blockIdx.x / nC;
    const int c = blockIdx.x % nC;

    const float ms  = msp[0];
    const float g   = lng[d];
    const float be  = lnb[d];
    const float inv = rsqrtf((float)D);

    const int lane = d & 31;
    const int w    = d >> 5;
    const int nw   = blockDim.x >> 5;

    __shared__ float red1[32], red2[32];

    float mr = 0.f, mi = 0.f;
    size_t base  = ((size_t)b * S + (size_t)c * CH) * D + d;
    size_t pbase = ((size_t)c * CH) * D + d;

    for (int s = 0; s < CH; s++) {
        size_t idx  = base + (size_t)s * D;
        size_t pidx = pbase + (size_t)s * D;

        float cbp = cb[pidx];
        float sbp = sbp_[pidx];
        float dk = KM[idx] * ms;
        float dq = QM[idx] * ms;
        float sk, ck, sq, cq;
        sincos_small(dk, sk, ck);
        sincos_small(dq, sq, cq);

        float ckp = cbp * ck - sbp * sk;
        float skp = sbp * ck + cbp * sk;
        float cqp = cbp * cq - sbp * sq;
        float sqp = sbp * cq + cbp * sq;

        float v = V[idx];
        mr = fmaf(v, ckp, mr);
        mi = fmaf(v, skp, mi);

        float r = (mr * cqp + mi * sqp) * inv;

        float s1 = r, s2 = r * r;
        #pragma unroll
        for (int o = 16; o > 0; o >>= 1) {
            s1 += __shfl_xor_sync(0xffffffffu, s1, o);
            s2 += __shfl_xor_sync(0xffffffffu, s2, o);
        }
        if (lane == 0) { red1[w] = s1; red2[w] = s2; }
        __syncthreads();
        if (d < 32) {
            float a1 = (d < nw) ? red1[d] : 0.f;
            float a2 = (d < nw) ? red2[d] : 0.f;
            #pragma unroll
            for (int o = 16; o > 0; o >>= 1) {
                a1 += __shfl_xor_sync(0xffffffffu, a1, o);
                a2 += __shfl_xor_sync(0xffffffffu, a2, o);
            }
            if (d == 0) { red1[0] = a1; red2[0] = a2; }
        }
        __syncthreads();
        float mu  = red1[0] / (float)D;
        float var = red2[0] / (float)D - mu * mu;
        __syncthreads();

        float normed = (r - mu) * rsqrtf(var + 1e-5f) * g + be;
        Oh[idx] = __float2half(normed);
    }
}

// ===========================================================================
// Launch
// ===========================================================================
extern "C" void kernel_launch(void* const* d_in, const int* in_sizes, int n_in,
                              void* d_out, int out_size)
{
    const float* x    = (const float*)d_in[0];
    const float* bp   = (const float*)d_in[1];
    const float* Wk   = (const float*)d_in[2];
    const float* bk   = (const float*)d_in[3];
    const float* Wv   = (const float*)d_in[4];
    const float* bv   = (const float*)d_in[5];
    const float* Wq   = (const float*)d_in[6];
    const float* bq   = (const float*)d_in[7];
    const float* Wkm  = (const float*)d_in[8];
    const float* bkm  = (const float*)d_in[9];
    const float* Wqm  = (const float*)d_in[10];
    const float* bqm  = (const float*)d_in[11];
    const float* ms   = (const float*)d_in[12];
    const float* lng  = (const float*)d_in[13];
    const float* lnb  = (const float*)d_in[14];
    const float* Wo   = (const float*)d_in[15];
    const float* bo   = (const float*)d_in[16];
    float* out = (float*)d_out;

    const int D  = in_sizes[3];         // 512
    const int SD = in_sizes[1];         // S*D
    const int S  = SD / D;              // 4096
    const int M  = in_sizes[0] / D;     // 16384
    const int CH = 64;

    __half* hp = nullptr;
    cudaGetSymbolAddress((void**)&hp, g_h);
    float* f32p = nullptr;
    cudaGetSymbolAddress((void**)&f32p, g_f32);
    __half* whp = nullptr;
    cudaGetSymbolAddress((void**)&whp, g_wh);
    float* cbuf = nullptr;
    cudaGetSymbolAddress((void**)&cbuf, g_cb);
    float* sbuf = nullptr;
    cudaGetSymbolAddress((void**)&sbuf, g_sb);

    __half* xh  = hp + 0L * MAXELEM;
    __half* Kh  = hp + 1L * MAXELEM;
    __half* Qh  = hp + 2L * MAXELEM;
    __half* NBh = hp + 3L * MAXELEM;

    float* V  = f32p + 0L * MAXELEM;
    float* KM = f32p + 1L * MAXELEM;
    float* QM = f32p + 2L * MAXELEM;

    const float* Ws[6] = { Wk, Wv, Wq, Wkm, Wqm, Wo };
    __half* Wh[6];
    for (int j = 0; j < 6; j++) Wh[j] = whp + (size_t)j * WELEM;

    cudaFuncSetAttribute(gemm_h, cudaFuncAttributeMaxDynamicSharedMemorySize,
                         GEMM_SMEM);

    // phase table + fp16 conversions
    phase_table_kernel<<<(SD + 255) / 256, 256>>>(bp, cbuf, sbuf, SD);
    tohalf_kernel<<<(M * D / 4 + 255) / 256, 256>>>(
        (const float4*)x, (__half2*)xh, M * D / 4);
    for (int j = 0; j < 6; j++)
        tohalf_kernel<<<(D * D / 4 + 255) / 256, 256>>>(
            (const float4*)Ws[j], (__half2*)Wh[j], D * D / 4);

    dim3 gg(D / 128, M / 128);   // (4, 128)

    // K = x@Wk^T + bk -> fp16
    gemm_h<<<gg, 256, GEMM_SMEM>>>(xh, Wh[0], bk, nullptr, nullptr, Kh,
                                   M, D, D, 1);
    // V = x@Wv^T + bv -> fp32
    gemm_h<<<gg, 256, GEMM_SMEM>>>(xh, Wh[1], bv, nullptr, V, nullptr,
                                   M, D, D, 0);
    // Q = x@Wq^T + bq -> fp16
    gemm_h<<<gg, 256, GEMM_SMEM>>>(xh, Wh[2], bq, nullptr, nullptr, Qh,
                                   M, D, D, 1);
    // KM = K@Wkm^T + bkm -> fp32
    gemm_h<<<gg, 256, GEMM_SMEM>>>(Kh, Wh[3], bkm, nullptr, KM, nullptr,
                                   M, D, D, 0);
    // QM = Q@Wqm^T + bqm -> fp32
    gemm_h<<<gg, 256, GEMM_SMEM>>>(Qh, Wh[4], bqm, nullptr, QM, nullptr,
                                   M, D, D, 0);

    // phasor + cumsum + retrieval + LayerNorm -> fp16
    phasor_ln_kernel<<<(M / CH), D>>>(V, KM, QM, cbuf, sbuf, ms, lng, lnb,
                                      NBh, S, D, CH);

    // out = x + normed@Wo^T + bo
    gemm_h<<<gg, 256, GEMM_SMEM>>>(NBh, Wh[5], bo, x, out, nullptr,
                                   M, D, D, 2);
}

// round 4
// speedup vs baseline: 5.6177x; 1.2124x over previous
#include <cuda_runtime.h>
#include <cuda_fp16.h>
#include <math.h>
#include <stdint.h>

// ===========================================================================
// Scratch (device globals; no allocation allowed)
// B=4, S=4096, D=512 -> M = 16384
// ===========================================================================
#define MAXELEM (16384 * 512)
#define MAXPH   (4096 * 512)
#define WELEM   (512 * 512)

__device__ __align__(256) __half g_h[6][MAXELEM];    // xh, Kh, Qh, NBh, KMh, QMh
__device__ __align__(256) float  g_V[MAXELEM];       // V (fp32)
__device__ __align__(256) __half g_wh[6][WELEM];     // 6 fp16 weights
__device__ float g_cb[MAXPH];
__device__ float g_sb[MAXPH];

// ===========================================================================
// helpers
// ===========================================================================
__device__ __forceinline__ uint32_t smem_to_u32(const void* smem_ptr) {
    uint32_t addr;
    asm("{ .reg .u64 tmp; cvta.to.shared.u64 tmp, %1; cvt.u32.u64 %0, tmp; }"
        : "=r"(addr) : "l"(smem_ptr));
    return addr;
}

__device__ __forceinline__ void ldsm_x4(uint32_t& r0, uint32_t& r1,
                                        uint32_t& r2, uint32_t& r3, uint32_t a) {
    asm volatile("ldmatrix.sync.aligned.m8n8.x4.shared.b16 {%0,%1,%2,%3}, [%4];\n"
                 : "=r"(r0), "=r"(r1), "=r"(r2), "=r"(r3) : "r"(a));
}

__device__ __forceinline__ void mma16816(float* c, const uint32_t* a,
                                         const uint32_t* b) {
    asm volatile(
        "mma.sync.aligned.m16n8k16.row.col.f32.f16.f16.f32 "
        "{%0,%1,%2,%3},{%4,%5,%6,%7},{%8,%9},{%0,%1,%2,%3};\n"
        : "+f"(c[0]), "+f"(c[1]), "+f"(c[2]), "+f"(c[3])
        : "r"(a[0]), "r"(a[1]), "r"(a[2]), "r"(a[3]), "r"(b[0]), "r"(b[1]));
}

// ===========================================================================
// base-phase cos/sin table
// ===========================================================================
__global__ void phase_table_kernel(const float* __restrict__ bp,
                                   float* __restrict__ cb,
                                   float* __restrict__ sb, int n) {
    int i = blockIdx.x * blockDim.x + threadIdx.x;
    if (i < n) {
        float s, c;
        sincosf(bp[i], &s, &c);
        cb[i] = c;
        sb[i] = s;
    }
}

// ===========================================================================
// fp32 -> fp16 (vectorized)
// ===========================================================================
__global__ void tohalf_kernel(const float4* __restrict__ src,
                              __half2* __restrict__ dst, int n4) {
    int i = blockIdx.x * blockDim.x + threadIdx.x;
    if (i < n4) {
        float4 v = src[i];
        dst[2 * i + 0] = __floats2half2_rn(v.x, v.y);
        dst[2 * i + 1] = __floats2half2_rn(v.z, v.w);
    }
}

// three fp32->fp16 conversions in one launch (equal length n4 per pair)
__global__ void tohalf3_kernel(const float4* s0, const float4* s1,
                               const float4* s2, __half2* d0, __half2* d1,
                               __half2* d2, int n4) {
    int i = blockIdx.x * blockDim.x + threadIdx.x;
    if (i >= 3 * n4) return;
    int t = i / n4, j = i - t * n4;
    const float4* s = (t == 0) ? s0 : (t == 1) ? s1 : s2;
    __half2* d = (t == 0) ? d0 : (t == 1) ? d1 : d2;
    float4 v = s[j];
    d[2 * j + 0] = __floats2half2_rn(v.x, v.y);
    d[2 * j + 1] = __floats2half2_rn(v.z, v.w);
}

// ===========================================================================
// fp16 HMMA GEMM (NT), batched via blockIdx.z job select.
// Tile 128x128, KC=64, 256 threads (8 warps 2x4, each 64x32),
// 2-stage cp.async pipeline, padded smem rows (144B).
// mode 0: outF = acc + bias
// mode 1: outH = fp16(acc + bias)
// mode 2: outF = acc + bias + resid
// ===========================================================================
#define KC 64
#define ROWB 144
#define TILE_B (128 * ROWB)
#define STAGE_B (2 * TILE_B)
#define GEMM_SMEM (2 * STAGE_B)    // 73728

struct Job {
    const __half* A;
    const __half* W;
    const float*  bias;
    const float*  resid;
    float*        outF;
    __half*       outH;
    int           mode;
};

__global__ __launch_bounds__(256, 2) void gemm_h(
    Job j0, Job j1, Job j2, int M, int N, int K)
{
    extern __shared__ char smem[];
    const Job jb = (blockIdx.z == 0) ? j0 : (blockIdx.z == 1) ? j1 : j2;

    const uint32_t sbase = smem_to_u32(smem);
    const int tid = threadIdx.x;
    const int wid = tid >> 5, lane = tid & 31;
    const int bm = blockIdx.y * 128;
    const int bn = blockIdx.x * 128;
    const int wm = wid >> 2, wn = wid & 3;
    const int NCH = K / KC;

    const __half* Ab = jb.A + (size_t)bm * K;
    const __half* Wb = jb.W + (size_t)bn * K;

    auto load_chunk = [&](int kc, int s) {
        uint32_t st = sbase + s * STAGE_B;
        int koff = kc * KC;
        #pragma unroll
        for (int j = 0; j < 8; j++) {
            int q = tid + j * 256;
            int t = q >> 10;
            int r = (q >> 3) & 127;
            int seg = q & 7;
            const __half* src = (t ? Wb : Ab) + (size_t)r * K + koff + seg * 8;
            uint32_t dst = st + t * TILE_B + r * ROWB + seg * 16;
            asm volatile("cp.async.cg.shared.global [%0], [%1], 16;\n"
                         :: "r"(dst), "l"(src));
        }
        asm volatile("cp.async.commit_group;\n");
    };

    float acc[4][4][4];
    #pragma unroll
    for (int i = 0; i < 4; i++)
        #pragma unroll
        for (int j = 0; j < 4; j++)
            #pragma unroll
            for (int e = 0; e < 4; e++) acc[i][j][e] = 0.f;

    load_chunk(0, 0);
    load_chunk(1, 1);

    const uint32_t a_r = (lane & 15);
    const uint32_t a_k = (lane >> 4) * 16;
    const uint32_t b_r = (lane & 7) + ((lane >> 4) << 3);
    const uint32_t b_k = ((lane >> 3) & 1) * 16;

    for (int i = 0; i < NCH; i++) {
        int s = i & 1;
        if (i == NCH - 1)
            asm volatile("cp.async.wait_group 0;\n" ::: "memory");
        else
            asm volatile("cp.async.wait_group 1;\n" ::: "memory");
        __syncthreads();

        uint32_t At = sbase + s * STAGE_B;
        uint32_t Wt = At + TILE_B;

        #pragma unroll
        for (int k16 = 0; k16 < 4; k16++) {
            uint32_t a[4][4];
            #pragma unroll
            for (int mi = 0; mi < 4; mi++) {
                uint32_t addr = At + (wm * 64 + mi * 16 + a_r) * ROWB
                              + k16 * 32 + a_k;
                ldsm_x4(a[mi][0], a[mi][1], a[mi][2], a[mi][3], addr);
            }
            uint32_t b[4][2];
            #pragma unroll
            for (int bp = 0; bp < 2; bp++) {
                uint32_t r0, r1, r2, r3;
                uint32_t addr = Wt + (wn * 32 + bp * 16 + b_r) * ROWB
                              + k16 * 32 + b_k;
                ldsm_x4(r0, r1, r2, r3, addr);
                b[2 * bp + 0][0] = r0; b[2 * bp + 0][1] = r1;
                b[2 * bp + 1][0] = r2; b[2 * bp + 1][1] = r3;
            }
            #pragma unroll
            for (int mi = 0; mi < 4; mi++)
                #pragma unroll
                for (int ni = 0; ni < 4; ni++)
                    mma16816(acc[mi][ni], a[mi], b[ni]);
        }
        __syncthreads();
        if (i + 2 < NCH) load_chunk(i + 2, s);
    }

    // epilogue
    const int r0 = bm + wm * 64 + (lane >> 2);
    const int c0 = bn + wn * 32 + (lane & 3) * 2;
    const int mode = jb.mode;
    #pragma unroll
    for (int mi = 0; mi < 4; mi++) {
        #pragma unroll
        for (int h = 0; h < 2; h++) {
            int row = r0 + mi * 16 + h * 8;
            #pragma unroll
            for (int ni = 0; ni < 4; ni++) {
                int col = c0 + ni * 8;
                size_t idx = (size_t)row * N + col;
                float2 bv = *(const float2*)(jb.bias + col);
                float v0 = acc[mi][ni][2 * h + 0] + bv.x;
                float v1 = acc[mi][ni][2 * h + 1] + bv.y;
                if (mode == 2) {
                    float2 rv = *(const float2*)(jb.resid + idx);
                    v0 += rv.x; v1 += rv.y;
                }
                if (mode == 1) {
                    *(__half2*)(jb.outH + idx) = __floats2half2_rn(v0, v1);
                } else {
                    float2 o; o.x = v0; o.y = v1;
                    *(float2*)(jb.outF + idx) = o;
                }
            }
        }
    }
}

// ===========================================================================
// Taylor sincos for tiny delta
// ===========================================================================
__device__ __forceinline__ void sincos_small(float x, float& s, float& c) {
    float x2 = x * x;
    s = x * fmaf(x2, fmaf(x2, fmaf(x2, -1.f / 5040.f, 1.f / 120.f), -1.f / 6.f), 1.f);
    c = fmaf(x2, fmaf(x2, fmaf(x2, -1.f / 720.f, 1.f / 24.f), -0.5f), 1.f);
}

// ===========================================================================
// Fused phasor bind + chunked cumsum + retrieval + LayerNorm -> fp16.
// Block = one (batch, chunk), 512 threads = one per feature d.
// Only TWO block barriers: pass1 computes all 64 r values (registers) with
// warp-level partial LN sums; pass2 finalizes per-position mean/rstd; pass3
// normalizes + stores.
// ===========================================================================
#define CHK 64
#define NW  16          // 512 threads / 32

__global__ __launch_bounds__(512) void phasor_ln_kernel(
    const float* __restrict__ V, const __half* __restrict__ KM,
    const __half* __restrict__ QM,
    const float* __restrict__ cb, const float* __restrict__ sbt,
    const float* __restrict__ msp,
    const float* __restrict__ lng, const float* __restrict__ lnb,
    __half* __restrict__ Oh, int S, int D)
{
    const int d = threadIdx.x;
    const int nC = S / CHK;
    const int b = blockIdx.x / nC;
    const int c = blockIdx.x % nC;

    const float ms  = msp[0];
    const float g   = lng[d];
    const float be  = lnb[d];
    const float inv = rsqrtf((float)D);

    const int lane = d & 31;
    const int w    = d >> 5;

    __shared__ float sm1[CHK * 17];
    __shared__ float sm2[CHK * 17];
    __shared__ float smu[CHK];
    __shared__ float srs[CHK];

    float r[CHK];
    float mr = 0.f, mi = 0.f;
    size_t base  = ((size_t)b * S + (size_t)c * CHK) * D + d;
    size_t pbase = ((size_t)c * CHK) * D + d;

    #pragma unroll
    for (int s = 0; s < CHK; s++) {
        size_t idx  = base + (size_t)s * D;
        size_t pidx = pbase + (size_t)s * D;

        float cbp = cb[pidx];
        float sbp = sbt[pidx];
        float dk = __half2float(KM[idx]) * ms;
        float dq = __half2float(QM[idx]) * ms;
        float sk, ck, sq, cq;
        sincos_small(dk, sk, ck);
        sincos_small(dq, sq, cq);

        float ckp = cbp * ck - sbp * sk;
        float skp = sbp * ck + cbp * sk;
        float cqp = cbp * cq - sbp * sq;
        float sqp = sbp * cq + cbp * sq;

        float v = V[idx];
        mr = fmaf(v, ckp, mr);
        mi = fmaf(v, skp, mi);

        float rv = (mr * cqp + mi * sqp) * inv;
        r[s] = rv;

        float s1 = rv, s2 = rv * rv;
        #pragma unroll
        for (int o = 16; o > 0; o >>= 1) {
            s1 += __shfl_xor_sync(0xffffffffu, s1, o);
            s2 += __shfl_xor_sync(0xffffffffu, s2, o);
        }
        if (lane == 0) { sm1[s * 17 + w] = s1; sm2[s * 17 + w] = s2; }
    }
    __syncthreads();

    if (d < CHK) {
        float a1 = 0.f, a2 = 0.f;
        #pragma unroll
        for (int j = 0; j < NW; j++) {
            a1 += sm1[d * 17 + j];
            a2 += sm2[d * 17 + j];
        }
        float mu = a1 / (float)D;
        smu[d] = mu;
        srs[d] = rsqrtf(a2 / (float)D - mu * mu + 1e-5f);
    }
    __syncthreads();

    #pragma unroll
    for (int s = 0; s < CHK; s++) {
        float normed = (r[s] - smu[s]) * srs[s] * g + be;
        Oh[base + (size_t)s * D] = __float2half(normed);
    }
}

// ===========================================================================
// Launch
// ===========================================================================
extern "C" void kernel_launch(void* const* d_in, const int* in_sizes, int n_in,
                              void* d_out, int out_size)
{
    const float* x    = (const float*)d_in[0];
    const float* bp   = (const float*)d_in[1];
    const float* Wk   = (const float*)d_in[2];
    const float* bk   = (const float*)d_in[3];
    const float* Wv   = (const float*)d_in[4];
    const float* bv   = (const float*)d_in[5];
    const float* Wq   = (const float*)d_in[6];
    const float* bq   = (const float*)d_in[7];
    const float* Wkm  = (const float*)d_in[8];
    const float* bkm  = (const float*)d_in[9];
    const float* Wqm  = (const float*)d_in[10];
    const float* bqm  = (const float*)d_in[11];
    const float* ms   = (const float*)d_in[12];
    const float* lng  = (const float*)d_in[13];
    const float* lnb  = (const float*)d_in[14];
    const float* Wo   = (const float*)d_in[15];
    const float* bo   = (const float*)d_in[16];
    float* out = (float*)d_out;

    const int D  = in_sizes[3];         // 512
    const int SD = in_sizes[1];         // S*D
    const int S  = SD / D;              // 4096
    const int M  = in_sizes[0] / D;     // 16384

    __half* hp = nullptr;   cudaGetSymbolAddress((void**)&hp, g_h);
    float* V = nullptr;     cudaGetSymbolAddress((void**)&V, g_V);
    __half* whp = nullptr;  cudaGetSymbolAddress((void**)&whp, g_wh);
    float* cbuf = nullptr;  cudaGetSymbolAddress((void**)&cbuf, g_cb);
    float* sbuf = nullptr;  cudaGetSymbolAddress((void**)&sbuf, g_sb);

    __half* xh  = hp + 0L * MAXELEM;
    __half* Kh  = hp + 1L * MAXELEM;
    __half* Qh  = hp + 2L * MAXELEM;
    __half* NBh = hp + 3L * MAXELEM;
    __half* KMh = hp + 4L * MAXELEM;
    __half* QMh = hp + 5L * MAXELEM;

    __half* Wh[6];
    for (int j = 0; j < 6; j++) Wh[j] = whp + (size_t)j * WELEM;

    cudaFuncSetAttribute(gemm_h, cudaFuncAttributeMaxDynamicSharedMemorySize,
                         GEMM_SMEM);

    const int W4 = WELEM / 4;

    // 0: x -> fp16
    tohalf_kernel<<<(M * D / 4 + 255) / 256, 256>>>(
        (const float4*)x, (__half2*)xh, M * D / 4);
    // 1: Wk, Wv, Wq -> fp16
    tohalf3_kernel<<<(3 * W4 + 255) / 256, 256>>>(
        (const float4*)Wk, (const float4*)Wv, (const float4*)Wq,
        (__half2*)Wh[0], (__half2*)Wh[1], (__half2*)Wh[2], W4);
    // 2: Wkm, Wqm, Wo -> fp16
    tohalf3_kernel<<<(3 * W4 + 255) / 256, 256>>>(
        (const float4*)Wkm, (const float4*)Wqm, (const float4*)Wo,
        (__half2*)Wh[3], (__half2*)Wh[4], (__half2*)Wh[5], W4);
    // 3: phase table
    phase_table_kernel<<<(SD + 255) / 256, 256>>>(bp, cbuf, sbuf, SD);

    dim3 g3(D / 128, M / 128, 3);
    dim3 g2(D / 128, M / 128, 2);
    dim3 g1(D / 128, M / 128, 1);

    Job jK  = { xh,  Wh[0], bk,  nullptr, nullptr, Kh,  1 };
    Job jV  = { xh,  Wh[1], bv,  nullptr, V,       nullptr, 0 };
    Job jQ  = { xh,  Wh[2], bq,  nullptr, nullptr, Qh,  1 };
    Job jKM = { Kh,  Wh[3], bkm, nullptr, nullptr, KMh, 1 };
    Job jQM = { Qh,  Wh[4], bqm, nullptr, nullptr, QMh, 1 };
    Job jO  = { NBh, Wh[5], bo,  x,       out,     nullptr, 2 };

    // 4: K, V, Q
    gemm_h<<<g3, 256, GEMM_SMEM>>>(jK, jV, jQ, M, D, D);
    // 5: KM, QM   (<- ncu -s 5 profiles this launch)
    gemm_h<<<g2, 256, GEMM_SMEM>>>(jKM, jQM, jQM, M, D, D);
    // 6: phasor + cumsum + retrieval + LayerNorm
    phasor_ln_kernel<<<(M / CHK), D>>>(V, KMh, QMh, cbuf, sbuf, ms, lng, lnb,
                                       NBh, S, D);
    // 7: out = x + normed@Wo^T + bo
    gemm_h<<<g1, 256, GEMM_SMEM>>>(jO, jO, jO, M, D, D);
}